// round 14
// baseline (speedup 1.0000x reference)
#include <cuda_runtime.h>
#include <cstdint>

// Screen / tiling constants (W=1280, H=720 are exact multiples of L=16)
#define W_SCREEN 1280.0f
#define H_SCREEN 720.0f
#define NBW      80
#define NBH      45
#define N_POINTS 32768
#define ROWS_PER_CTA 9          // 45 = 5 * 9
#define BANDS    5
#define N_CHUNKS 64             // 512 points per chunk
#define ITEMS_PER_CHUNK (NBW * BANDS)   // 400 CTAs share one chunk's table
#define SPIN_BUDGET 20000       // bounded spin iterations before fallback

// Per-point tile intervals packed into one uint32:
//   byte0 = a (first valid yi)  byte1 = n  (y-interval length)
//   byte2 = ax0 (first valid xi) byte3 = nx (last-first xi)
__device__ __align__(16) unsigned g_packed[N_POINTS];
__device__ int g_flag[N_CHUNKS];    // 0 -> 1 when chunk's table ready (self-resets)
__device__ int g_count[N_CHUNKS];   // per-chunk completion counter (self-resets)

// Compute one thread's 4 packed intervals straight from inputs (R5 prolog).
// Reference condition per (tile, point) reduces (right=left+16, bottom=top+16
// exact; xmax>xmin, ymax>ymin since radius>=1) to the separable test:
//   x: (unsigned)(xi - ax0) <= nx,   y: (unsigned)(yi - a) < n.
__device__ __forceinline__ void compute_packed4(
        const float* __restrict__ pos2d, const float* __restrict__ radius,
        int g, unsigned w[4]) {
    float4 q01 = reinterpret_cast<const float4*>(pos2d)[2 * g];
    float4 q23 = reinterpret_cast<const float4*>(pos2d)[2 * g + 1];
    float4 r4  = reinterpret_cast<const float4*>(radius)[g];
    float xs[4] = {q01.x, q01.z, q23.x, q23.z};
    float ys[4] = {q01.y, q01.w, q23.y, q23.w};
    float rs[4] = {r4.x, r4.y, r4.z, r4.w};
#pragma unroll
    for (int j = 0; j < 4; j++) {
        float x = xs[j], y = ys[j], r = rs[j];
        int xmin = (int)fminf(fmaxf(x - r, 0.0f), W_SCREEN);
        int xmax = (int)fminf(fmaxf(x + r, 0.0f), W_SCREEN);
        int ymin = (int)fminf(fmaxf(y - r, 0.0f), H_SCREEN);
        int ymax = (int)fminf(fmaxf(y + r, 0.0f), H_SCREEN);
        unsigned aj  = (unsigned)(ymin >> 4);
        unsigned nj  = (unsigned)(((ymax - 1) >> 4) + 1) - aj;
        unsigned ax0 = (unsigned)(xmin >> 4);
        unsigned nx  = (unsigned)((xmax - 1) >> 4) - ax0;
        w[j] = aj | (nj << 8) | (ax0 << 16) | (nx << 24);
    }
}

// Single kernel. Grid (64 chunks, 80 xi, 5 bands), block 128, 4 pts/thread.
// Producer CTAs (y==0 && z==0; linear block ids 0..63 -> wave-1 resident)
// compute their chunk's packed table, publish, set flag. Consumers spin with
// a BOUNDED budget; on timeout they fall back to computing their own
// intervals (identical values either way -> deterministic output, no hang).
// The 400th finishing CTA per chunk resets flag/count for graph replay.
__global__ __launch_bounds__(128) void fused_spin_mask_kernel(
        const float* __restrict__ pos2d,
        const float* __restrict__ radius,
        float* __restrict__ out) {
    int t     = threadIdx.x;          // 0..127
    int chunk = blockIdx.x;           // 0..63
    int xi    = blockIdx.y;           // 0..79
    int y0    = blockIdx.z * ROWS_PER_CTA;
    int g     = chunk * 128 + t;      // 4-point group, 0..8191

    __shared__ int s_ready;
    unsigned a[4], n[4];

    if (blockIdx.y == 0 && blockIdx.z == 0) {
        // ---- Producer: compute + publish chunk table, keep own copy.
        unsigned w[4];
        compute_packed4(pos2d, radius, g, w);
        reinterpret_cast<uint4*>(g_packed)[g] = make_uint4(w[0], w[1], w[2], w[3]);
        __threadfence();                 // publish table before flag (release)
        __syncthreads();
        if (t == 0) atomicExch(&g_flag[chunk], 1);
#pragma unroll
        for (int j = 0; j < 4; j++) {
            a[j] = w[j] & 0xFFu;
            unsigned ax0 = (w[j] >> 16) & 0xFFu;
            n[j] = (ax0 == 0u) ? ((w[j] >> 8) & 0xFFu) : 0u;   // xi == 0 here
        }
    } else {
        // ---- Consumer: bounded wait, fallback to self-compute on timeout.
        if (t == 0) {
            int f = atomicAdd(&g_flag[chunk], 0);
            int it = 0;
            while (f == 0 && it < SPIN_BUDGET) {
                __nanosleep(64);
                f = atomicAdd(&g_flag[chunk], 0);
                it++;
            }
            if (f) __threadfence();      // acquire
            s_ready = f;
        }
        __syncthreads();
        unsigned w[4];
        if (s_ready) {
            uint4 pk = __ldcg(reinterpret_cast<const uint4*>(g_packed) + g);
            w[0] = pk.x; w[1] = pk.y; w[2] = pk.z; w[3] = pk.w;
        } else {
            compute_packed4(pos2d, radius, g, w);   // hang-proof fallback
        }
#pragma unroll
        for (int j = 0; j < 4; j++) {
            a[j] = w[j] & 0xFFu;
            unsigned ax0 = (w[j] >> 16) & 0xFFu;
            unsigned nx  = w[j] >> 24;
            n[j] = ((unsigned)(xi - ax0) <= nx) ? ((w[j] >> 8) & 0xFFu) : 0u;
        }
    }

    float* optr = out + ((size_t)xi * NBH + y0) * N_POINTS + (size_t)g * 4;

#pragma unroll
    for (int k = 0; k < ROWS_PER_CTA; k++) {
        int yi = y0 + k;
        float4 v;
        v.x = ((unsigned)(yi - a[0]) < n[0]) ? 1.0f : 0.0f;
        v.y = ((unsigned)(yi - a[1]) < n[1]) ? 1.0f : 0.0f;
        v.z = ((unsigned)(yi - a[2]) < n[2]) ? 1.0f : 0.0f;
        v.w = ((unsigned)(yi - a[3]) < n[3]) ? 1.0f : 0.0f;
        __stcs(reinterpret_cast<float4*>(optr), v);   // streaming store
        optr += N_POINTS;
    }

    // ---- Replay-safe reset: last CTA of this chunk clears flag + counter.
    __syncthreads();
    if (t == 0) {
        int done = atomicAdd(&g_count[chunk], 1);
        if (done == ITEMS_PER_CHUNK - 1) {
            g_count[chunk] = 0;
            __threadfence();
            atomicExch(&g_flag[chunk], 0);
        }
    }
}

extern "C" void kernel_launch(void* const* d_in, const int* in_sizes, int n_in,
                              void* d_out, int out_size) {
    const float* pos2d  = (const float*)d_in[0];   // [32768, 2] float32
    const float* radius = (const float*)d_in[1];   // [32768]    float32
    float* out          = (float*)d_out;           // [3600, 32768] float32

    dim3 grid(N_CHUNKS, NBW, BANDS);               // 64 x 80 x 5 = 25600 CTAs
    fused_spin_mask_kernel<<<grid, 128>>>(pos2d, radius, out);
}

// round 15
// speedup vs baseline: 1.1198x; 1.1198x over previous
#include <cuda_runtime.h>
#include <cstdint>

// Screen / tiling constants (W=1280, H=720 are exact multiples of L=16)
#define W_SCREEN 1280.0f
#define H_SCREEN 720.0f
#define NBW      80
#define NBH      45
#define N_POINTS 32768
#define ROWS_PER_CTA 9     // 45 = 5 * 9
#define BANDS    5

// R5 champion structure, one change: __stcs streaming stores.
// One block per (512-point chunk, xi column, 9-row band). Each thread owns 4
// consecutive points, computes their AABB -> tile-row interval [a, a+n) in
// the prolog (n = 0 when this xi column misses the point's x-interval), then
// sweeps its 9 rows emitting one float4 (STG.128, evict-first) per row.
//
// Reference condition per (tile, point):
//   min(xmax,right) > max(xmin,left) && min(ymax,bottom) > max(ymin,top)
// With right=left+16, bottom=top+16 exact (W,H multiples of 16) and
// xmax>xmin, ymax>ymin guaranteed (radius >= 1), this reduces to the
// separable interval test; the y part becomes (unsigned)(yi - a) < n.
__global__ __launch_bounds__(128) void fused_mask_kernel(
        const float* __restrict__ pos2d,
        const float* __restrict__ radius,
        float* __restrict__ out) {
    int g  = blockIdx.x * 128 + threadIdx.x;   // 4-point group, 0..8191
    int xi = blockIdx.y;                       // 0..79
    int y0 = blockIdx.z * ROWS_PER_CTA;        // 0, 9, 18, 27, 36
    int left  = xi * 16;
    int right = left + 16;

    // Load this thread's 4 points (48 bytes, fully coalesced; L2-resident).
    float4 q01 = reinterpret_cast<const float4*>(pos2d)[2 * g];      // pts 4g,4g+1
    float4 q23 = reinterpret_cast<const float4*>(pos2d)[2 * g + 1];  // pts 4g+2,4g+3
    float4 r4  = reinterpret_cast<const float4*>(radius)[g];

    unsigned a[4], n[4];
    {
        float xs[4] = {q01.x, q01.z, q23.x, q23.z};
        float ys[4] = {q01.y, q01.w, q23.y, q23.w};
        float rs[4] = {r4.x, r4.y, r4.z, r4.w};
#pragma unroll
        for (int j = 0; j < 4; j++) {
            float x = xs[j], y = ys[j], r = rs[j];
            int xmin = (int)fminf(fmaxf(x - r, 0.0f), W_SCREEN);
            int xmax = (int)fminf(fmaxf(x + r, 0.0f), W_SCREEN);
            int ymin = (int)fminf(fmaxf(y - r, 0.0f), H_SCREEN);
            int ymax = (int)fminf(fmaxf(y + r, 0.0f), H_SCREEN);

            bool okx = (xmax > left) && (xmin < right);
            unsigned aj = (unsigned)(ymin >> 4);               // first valid yi
            unsigned bj = (unsigned)(((ymax - 1) >> 4) + 1);   // one past last
            a[j] = aj;
            n[j] = okx ? (bj - aj) : 0u;                       // interval length
        }
    }

    float* optr = out + ((size_t)xi * NBH + y0) * N_POINTS + (size_t)g * 4;

#pragma unroll
    for (int k = 0; k < ROWS_PER_CTA; k++) {
        int yi = y0 + k;
        float4 v;
        v.x = ((unsigned)(yi - a[0]) < n[0]) ? 1.0f : 0.0f;
        v.y = ((unsigned)(yi - a[1]) < n[1]) ? 1.0f : 0.0f;
        v.z = ((unsigned)(yi - a[2]) < n[2]) ? 1.0f : 0.0f;
        v.w = ((unsigned)(yi - a[3]) < n[3]) ? 1.0f : 0.0f;
        __stcs(reinterpret_cast<float4*>(optr), v);   // streaming, zero reuse
        optr += N_POINTS;
    }
}

extern "C" void kernel_launch(void* const* d_in, const int* in_sizes, int n_in,
                              void* d_out, int out_size) {
    const float* pos2d  = (const float*)d_in[0];   // [32768, 2] float32
    const float* radius = (const float*)d_in[1];   // [32768]    float32
    float* out          = (float*)d_out;           // [3600, 32768] float32

    dim3 grid(64, NBW, BANDS);                     // 64 chunks x 80 xi x 5 bands
    fused_mask_kernel<<<grid, 128>>>(pos2d, radius, out);
}